// round 15
// baseline (speedup 1.0000x reference)
#include <cuda_runtime.h>
#include <cuda_bf16.h>
#include <cstdint>

// ---------------- problem constants ----------------
#define B_DIM    64
#define C_DIM    512
#define T_DIM    256
#define Q_LAYERS 6
#define K_CODES  1024
#define M_TOT    (B_DIM * T_DIM)                    // 16384
#define OUT_QOUT_ELEMS (B_DIM * C_DIM * T_DIM)      // 8388608
#define OUT_IDX_ELEMS  (B_DIM * T_DIM * Q_LAYERS)   // 98304

// ---------------- GEMM tiling (bf16, 2-stage, KC=64) ----------------
#define M_TILE   64
#define N_TILE   256
#define N_PASSES (K_CODES / N_TILE)  // 4
#define KC       64                  // bf16 k-elems per staged chunk (128B/row)
#define K_CHUNKS (C_DIM / KC)        // 8 per pass
#define TOT_CHUNKS (N_PASSES * K_CHUNKS)  // 32 per layer
#define ROWB     144                 // 128B data + 16B pad (conflict-free ldmatrix)
#define A_BYTES  (M_TILE * ROWB)     // 9216
#define B_BYTES  (N_TILE * ROWB)     // 36864
#define STAGE_BYTES (A_BYTES + B_BYTES)      // 46080
#define MERGE_OFF   (2 * STAGE_BYTES)        // 92160
#define SMEM_BYTES  (MERGE_OFF + 9280)       // 101440 (2 CTAs/SM)

// ---------------- device scratch ----------------
__device__ __align__(16) float          g_X [M_TOT * C_DIM];
__device__ __align__(16) __nv_bfloat16  g_Xb[M_TOT * C_DIM];
__device__ __align__(16) __nv_bfloat16  g_CBb[Q_LAYERS * K_CODES * C_DIM];
__device__ int    g_idx[Q_LAYERS * M_TOT];
__device__ float  g_norm[Q_LAYERS * K_CODES];
__device__ int    g_hist[Q_LAYERS * K_CODES];
__device__ double g_commit[Q_LAYERS];

// ---------------- helpers ----------------
__device__ __forceinline__ uint32_t smem_u32(const void* p) {
    uint32_t a;
    asm("{ .reg .u64 t; cvta.to.shared.u64 t, %1; cvt.u32.u64 %0, t; }" : "=r"(a) : "l"(p));
    return a;
}
__device__ __forceinline__ void cp_async16(uint32_t dst, const void* src) {
    asm volatile("cp.async.cg.shared.global [%0], [%1], 16;" :: "r"(dst), "l"(src));
}
__device__ __forceinline__ void cp_commit() {
    asm volatile("cp.async.commit_group;" ::: "memory");
}
template <int N> __device__ __forceinline__ void cp_wait() {
    asm volatile("cp.async.wait_group %0;" :: "n"(N) : "memory");
}
__device__ __forceinline__ void ldsm_x4(uint32_t& r0, uint32_t& r1,
                                        uint32_t& r2, uint32_t& r3, uint32_t addr) {
    asm volatile("ldmatrix.sync.aligned.m8n8.x4.shared.b16 {%0,%1,%2,%3}, [%4];"
                 : "=r"(r0), "=r"(r1), "=r"(r2), "=r"(r3) : "r"(addr));
}
__device__ __forceinline__ void mma_bf16(float* c, const uint32_t* a,
                                         uint32_t b0, uint32_t b1) {
    asm volatile(
        "mma.sync.aligned.m16n8k16.row.col.f32.bf16.bf16.f32 "
        "{%0,%1,%2,%3}, {%4,%5,%6,%7}, {%8,%9}, {%0,%1,%2,%3};"
        : "+f"(c[0]), "+f"(c[1]), "+f"(c[2]), "+f"(c[3])
        : "r"(a[0]), "r"(a[1]), "r"(a[2]), "r"(a[3]), "r"(b0), "r"(b1));
}

__device__ __forceinline__ void ins4(float s, int n, float v[4], int ix[4]) {
    if (s < v[3]) {
        if (s < v[1]) {
            if (s < v[0]) { v[3]=v[2];ix[3]=ix[2]; v[2]=v[1];ix[2]=ix[1];
                            v[1]=v[0];ix[1]=ix[0]; v[0]=s;ix[0]=n; }
            else          { v[3]=v[2];ix[3]=ix[2]; v[2]=v[1];ix[2]=ix[1];
                            v[1]=s;ix[1]=n; }
        } else {
            if (s < v[2]) { v[3]=v[2];ix[3]=ix[2]; v[2]=s;ix[2]=n; }
            else          { v[3]=s;ix[3]=n; }
        }
    }
}
__device__ __forceinline__ bool lexlt(float s, int n, float v, int i) {
    return (s < v) || (s == v && n < i);
}
__device__ __forceinline__ void ins4lex(float s, int n, float v[4], int ix[4]) {
    if (lexlt(s, n, v[3], ix[3])) {
        if (lexlt(s, n, v[1], ix[1])) {
            if (lexlt(s, n, v[0], ix[0])) { v[3]=v[2];ix[3]=ix[2]; v[2]=v[1];ix[2]=ix[1];
                                            v[1]=v[0];ix[1]=ix[0]; v[0]=s;ix[0]=n; }
            else                          { v[3]=v[2];ix[3]=ix[2]; v[2]=v[1];ix[2]=ix[1];
                                            v[1]=s;ix[1]=n; }
        } else {
            if (lexlt(s, n, v[2], ix[2])) { v[3]=v[2];ix[3]=ix[2]; v[2]=s;ix[2]=n; }
            else                          { v[3]=s;ix[3]=n; }
        }
    }
}

// ---------------------------------------------------------------------------
// 1) prep: transpose x -> g_X/g_Xb  AND  norms + bf16 codebook
// ---------------------------------------------------------------------------
#define PREP_TR_BLOCKS 8192
#define PREP_BLOCKS    (PREP_TR_BLOCKS + Q_LAYERS * K_CODES)

__global__ __launch_bounds__(256) void prep_kernel(
    const float* __restrict__ x, const float* __restrict__ codebooks)
{
    __shared__ float sred[32 * 33];
    const int bid = blockIdx.x;
    const int tid = threadIdx.x;

    if (bid < PREP_TR_BLOCKS) {
        const int b  = bid >> 7;
        const int r  = bid & 127;
        const int c0 = (r >> 3) * 32;
        const int t0 = (r & 7) * 32;
        const int tx = tid & 31;
        const int ty = tid >> 5;
        float (*tile)[33] = reinterpret_cast<float(*)[33]>(sred);

        const float* xp = x + (size_t)b * C_DIM * T_DIM;
#pragma unroll
        for (int i = ty; i < 32; i += 8)
            tile[i][tx] = xp[(size_t)(c0 + i) * T_DIM + t0 + tx];
        __syncthreads();
#pragma unroll
        for (int i = ty; i < 32; i += 8) {
            const float vv = tile[tx][i];
            const size_t o = (size_t)(b * T_DIM + t0 + i) * C_DIM + c0 + tx;
            g_X[o]  = vv;
            g_Xb[o] = __float2bfloat16(vv);
        }
    } else {
        const int gk = bid - PREP_TR_BLOCKS;            // 0 .. 6143
        const float2 c = reinterpret_cast<const float2*>(codebooks + (size_t)gk * C_DIM)[tid];
        sred[tid] = c.x * c.x + c.y * c.y;
        __nv_bfloat162 h = {__float2bfloat16(c.x), __float2bfloat16(c.y)};
        reinterpret_cast<__nv_bfloat162*>(g_CBb + (size_t)gk * C_DIM)[tid] = h;
        __syncthreads();
        for (int off = 128; off > 0; off >>= 1) {
            if (tid < off) sred[tid] += sred[tid + off];
            __syncthreads();
        }
        if (tid == 0) {
            g_norm[gk] = sred[0];
            if (gk < Q_LAYERS) g_commit[gk] = 0.0;
        }
    }
}

// ---------------------------------------------------------------------------
// 2) Persistent fused kernel: all 6 layers (bf16 mma) + cross-layer prestage
// ---------------------------------------------------------------------------
__device__ __forceinline__ void stage_A_chunk(uint32_t sbase, int buf, int cidx,
                                              int m0, int tid)
{
    const int kw = (cidx & 7) * KC;
    const uint32_t ab = sbase + (uint32_t)(buf * STAGE_BYTES);
#pragma unroll
    for (int i = 0; i < 2; ++i) {
        const int idx = tid + 256 * i;
        const int row = idx >> 3, g = idx & 7;
        cp_async16(ab + (uint32_t)(row * ROWB + g * 16),
                   g_Xb + (size_t)(m0 + row) * C_DIM + kw + g * 8);
    }
}
__device__ __forceinline__ void stage_B_chunk(uint32_t sbase, int buf, int cidx,
                                              const __nv_bfloat16* __restrict__ cbb,
                                              int tid)
{
    const int nt = cidx >> 3;
    const int kw = (cidx & 7) * KC;
    const uint32_t bb = sbase + (uint32_t)(buf * STAGE_BYTES) + A_BYTES;
    const __nv_bfloat16* bsrc = cbb + (size_t)(nt * N_TILE) * C_DIM + kw;
#pragma unroll
    for (int i = 0; i < 8; ++i) {
        const int idx = tid + 256 * i;
        const int row = idx >> 3, g = idx & 7;
        cp_async16(bb + (uint32_t)(row * ROWB + g * 16),
                   bsrc + (size_t)row * C_DIM + g * 8);
    }
}

__global__ __launch_bounds__(256, 2) void rvq_fused_kernel(
    const float* __restrict__ cbf0)
{
    extern __shared__ char sm[];
    const uint32_t sbase = smem_u32(sm);

    const int tid  = threadIdx.x;
    const int wid  = tid >> 5;
    const int lane = tid & 31;
    const int wr   = wid & 1;
    const int wc   = wid >> 1;
    const int lg   = lane >> 2;
    const int lt   = lane & 3;
    const int m0   = blockIdx.x * M_TILE;

    const uint32_t aoff0 = (uint32_t)((wr * 32 + (lane & 15)) * ROWB + (lane >> 4) * 16);
    const uint32_t aoff1 = aoff0 + 16 * ROWB;
    const uint32_t boff  = (uint32_t)((wc * 64 + (lane & 7) + ((lane >> 4) << 3)) * ROWB
                                      + (((lane >> 3) & 1) * 16));

    float* smV = (float*)(sm + MERGE_OFF);          // [4][64][4]
    int*   smI = (int*)(sm + MERGE_OFF + 4096);     // [4][64][4]
    int*   sFi = (int*)(sm + MERGE_OFF + 8192);     // [64][4]
    float* sCm = (float*)(sm + MERGE_OFF + 9216);   // [8]

    for (int q = 0; q < Q_LAYERS; ++q) {
        const __nv_bfloat16* __restrict__ cbb = g_CBb + (size_t)q * K_CODES * C_DIM;
        const float* __restrict__ cbf  = cbf0 + (size_t)q * K_CODES * C_DIM;
        const float* __restrict__ norms = g_norm + q * K_CODES;

        float v[4][4];
        int   ix[4][4];
#pragma unroll
        for (int r = 0; r < 4; ++r)
#pragma unroll
            for (int j = 0; j < 4; ++j) { v[r][j] = 3.4e38f; ix[r][j] = 0; }

        if (q == 0) {
            __syncthreads();
            stage_A_chunk(sbase, 0, 0, m0, tid);
            stage_B_chunk(sbase, 0, 0, cbb, tid);
            cp_commit();
        }
        // q > 0: chunk 0 prestaged across the layer boundary

        for (int nt = 0; nt < N_PASSES; ++nt) {
            float acc[2][8][4];
#pragma unroll
            for (int s = 0; s < 2; ++s)
#pragma unroll
                for (int ns = 0; ns < 8; ++ns)
#pragma unroll
                    for (int j = 0; j < 4; ++j) acc[s][ns][j] = 0.0f;

#pragma unroll 2
            for (int kc = 0; kc < K_CHUNKS; ++kc) {
                const int cidx = nt * K_CHUNKS + kc;
                cp_wait<0>();
                __syncthreads();
                if (cidx + 1 < TOT_CHUNKS) {
                    stage_A_chunk(sbase, (cidx + 1) & 1, cidx + 1, m0, tid);
                    stage_B_chunk(sbase, (cidx + 1) & 1, cidx + 1, cbb, tid);
                    cp_commit();
                }

                const uint32_t Ab = sbase + (uint32_t)((cidx & 1) * STAGE_BYTES);
                const uint32_t Bb = Ab + A_BYTES;

#pragma unroll
                for (int ks = 0; ks < 4; ++ks) {
                    const uint32_t kb = (uint32_t)(ks * 32);
                    uint32_t a[2][4];
                    ldsm_x4(a[0][0], a[0][1], a[0][2], a[0][3], Ab + aoff0 + kb);
                    ldsm_x4(a[1][0], a[1][1], a[1][2], a[1][3], Ab + aoff1 + kb);
#pragma unroll
                    for (int p = 0; p < 4; ++p) {
                        uint32_t b0, b1, b2, b3;
                        ldsm_x4(b0, b1, b2, b3, Bb + boff + (uint32_t)(p * 16 * ROWB) + kb);
                        mma_bf16(acc[0][2 * p    ], a[0], b0, b1);
                        mma_bf16(acc[1][2 * p    ], a[1], b0, b1);
                        mma_bf16(acc[0][2 * p + 1], a[0], b2, b3);
                        mma_bf16(acc[1][2 * p + 1], a[1], b2, b3);
                    }
                }
            }

            const int nbase = nt * N_TILE + wc * 64 + lt * 2;
#pragma unroll
            for (int s = 0; s < 2; ++s) {
#pragma unroll
                for (int ns = 0; ns < 8; ++ns) {
                    const int n = nbase + ns * 8;
                    const float nm0 = __ldg(&norms[n]);
                    const float nm1 = __ldg(&norms[n + 1]);
                    ins4(fmaf(-2.0f, acc[s][ns][0], nm0), n,     v[s*2+0], ix[s*2+0]);
                    ins4(fmaf(-2.0f, acc[s][ns][1], nm1), n + 1, v[s*2+0], ix[s*2+0]);
                    ins4(fmaf(-2.0f, acc[s][ns][2], nm0), n,     v[s*2+1], ix[s*2+1]);
                    ins4(fmaf(-2.0f, acc[s][ns][3], nm1), n + 1, v[s*2+1], ix[s*2+1]);
                }
            }
        }

#pragma unroll
        for (int r = 0; r < 4; ++r) {
#pragma unroll
            for (int o = 1; o <= 2; o <<= 1) {
                float ov[4]; int oi[4];
#pragma unroll
                for (int j = 0; j < 4; ++j) {
                    ov[j] = __shfl_xor_sync(0xffffffffu, v[r][j], o);
                    oi[j] = __shfl_xor_sync(0xffffffffu, ix[r][j], o);
                }
#pragma unroll
                for (int j = 0; j < 4; ++j) ins4lex(ov[j], oi[j], v[r], ix[r]);
            }
        }

        __syncthreads();
        if (lt == 0) {
#pragma unroll
            for (int r = 0; r < 4; ++r) {
                const int row = wr * 32 + (r >> 1) * 16 + (r & 1) * 8 + lg;
#pragma unroll
                for (int j = 0; j < 4; ++j) {
                    smV[(wc * 64 + row) * 4 + j] = v[r][j];
                    smI[(wc * 64 + row) * 4 + j] = ix[r][j];
                }
            }
        }
        __syncthreads();
        if (wid < 2) {
            const int row = wid * 32 + lane;
            float fv[4]; int fi[4];
#pragma unroll
            for (int j = 0; j < 4; ++j) { fv[j] = 3.4e38f; fi[j] = 0x7fffffff; }
#pragma unroll
            for (int h = 0; h < 4; ++h)
#pragma unroll
                for (int j = 0; j < 4; ++j)
                    ins4lex(smV[(h * 64 + row) * 4 + j], smI[(h * 64 + row) * 4 + j], fv, fi);
#pragma unroll
            for (int j = 0; j < 4; ++j) sFi[row * 4 + j] = fi[j];
        }
        __syncthreads();

        if (q + 1 < Q_LAYERS) {
            stage_B_chunk(sbase, 0, 0, g_CBb + (size_t)(q + 1) * K_CODES * C_DIM, tid);
            cp_commit();
        }

        // ---------------- exact fp32 fixup + residual update ----------------
        float warp_commit = 0.0f;
        int* hist_q = g_hist + q * K_CODES;

#pragma unroll 1
        for (int i = 0; i < 8; ++i) {
            const int row = wid * 8 + i;
            const int m   = m0 + row;
            int cand[4];
#pragma unroll
            for (int c = 0; c < 4; ++c) cand[c] = sFi[row * 4 + c];

            const float4* xp = reinterpret_cast<const float4*>(g_X + (size_t)m * C_DIM);
            float4 xv[4];
#pragma unroll
            for (int j = 0; j < 4; ++j) xv[j] = xp[lane + 32 * j];

            float d[4];
#pragma unroll
            for (int c = 0; c < 4; ++c) {
                const float4* cp = reinterpret_cast<const float4*>(cbf + (size_t)cand[c] * C_DIM);
                float s = 0.0f;
#pragma unroll
                for (int j = 0; j < 4; ++j) {
                    const float4 cv = cp[lane + 32 * j];
                    const float dx = xv[j].x - cv.x, dy = xv[j].y - cv.y;
                    const float dz = xv[j].z - cv.z, dw = xv[j].w - cv.w;
                    s += dx * dx + dy * dy + dz * dz + dw * dw;
                }
                d[c] = s;
            }
#pragma unroll
            for (int c = 0; c < 4; ++c)
#pragma unroll
                for (int o = 16; o > 0; o >>= 1)
                    d[c] += __shfl_xor_sync(0xffffffffu, d[c], o);

            float best = d[0]; int bi = cand[0];
#pragma unroll
            for (int c = 1; c < 4; ++c) {
                if (d[c] < best || (d[c] == best && cand[c] < bi)) {
                    best = d[c]; bi = cand[c];
                }
            }

            const float4* bp = reinterpret_cast<const float4*>(cbf + (size_t)bi * C_DIM);
            float4* xo = reinterpret_cast<float4*>(g_X + (size_t)m * C_DIM);
            uint2*  xb = reinterpret_cast<uint2*>(g_Xb + (size_t)m * C_DIM);
#pragma unroll
            for (int j = 0; j < 4; ++j) {
                const float4 cv = bp[lane + 32 * j];
                float4 r;
                r.x = xv[j].x - cv.x; r.y = xv[j].y - cv.y;
                r.z = xv[j].z - cv.z; r.w = xv[j].w - cv.w;
                xo[lane + 32 * j] = r;
                __nv_bfloat162 h0 = {__float2bfloat16(r.x), __float2bfloat16(r.y)};
                __nv_bfloat162 h1 = {__float2bfloat16(r.z), __float2bfloat16(r.w)};
                uint2 pk;
                pk.x = *reinterpret_cast<uint32_t*>(&h0);
                pk.y = *reinterpret_cast<uint32_t*>(&h1);
                xb[lane + 32 * j] = pk;
            }

            if (lane == 0) {
                warp_commit += best;
                g_idx[q * M_TOT + m] = bi;
                atomicAdd(&hist_q[bi], 1);
            }
        }

        if (lane == 0) sCm[wid] = warp_commit;
        __syncthreads();     // orders g_Xb writes before next-layer A staging (block scope)
        if (tid == 0) {
            float cs = 0.0f;
#pragma unroll
            for (int w = 0; w < 8; ++w) cs += sCm[w];
            atomicAdd(&g_commit[q], (double)cs);
        }

        if (q + 1 < Q_LAYERS) {
            stage_A_chunk(sbase, 0, 0, m0, tid);
            cp_commit();
        }
    }
}

// ---------------------------------------------------------------------------
// 3) finish: qout = x - final_residual (transposed), idx out, perp + scalars
// ---------------------------------------------------------------------------
#define FIN_QOUT_BLOCKS 8192
#define FIN_IDX_BLOCKS  (OUT_IDX_ELEMS / 256)       // 384
#define FIN_BLOCKS      (FIN_QOUT_BLOCKS + FIN_IDX_BLOCKS + 1)

__global__ __launch_bounds__(256) void finish_kernel(
    const float* __restrict__ x, float* __restrict__ out)
{
    const int bid = blockIdx.x;
    const int tid = threadIdx.x;

    if (bid < FIN_QOUT_BLOCKS) {
        __shared__ float tile[32][33];
        const int b  = bid >> 7;
        const int r  = bid & 127;
        const int c0 = (r >> 3) * 32;
        const int t0 = (r & 7) * 32;
        const int tx = tid & 31;
        const int ty = tid >> 5;

#pragma unroll
        for (int i = ty; i < 32; i += 8)
            tile[i][tx] = g_X[(size_t)(b * T_DIM + t0 + i) * C_DIM + c0 + tx];
        __syncthreads();

        const float* xp = x + (size_t)b * C_DIM * T_DIM;
        float* op = out + (size_t)b * C_DIM * T_DIM;
#pragma unroll
        for (int i = ty; i < 32; i += 8) {
            const size_t o = (size_t)(c0 + i) * T_DIM + t0 + tx;
            op[o] = xp[o] - tile[tx][i];
        }
    } else if (bid < FIN_QOUT_BLOCKS + FIN_IDX_BLOCKS) {
        const int i = (bid - FIN_QOUT_BLOCKS) * 256 + tid;
        const int m = i / Q_LAYERS;
        const int q = i - m * Q_LAYERS;
        out[OUT_QOUT_ELEMS + i] = (float)g_idx[q * M_TOT + m];
    } else {
        __shared__ float red[256];
        __shared__ float sperp[Q_LAYERS];
        for (int q = 0; q < Q_LAYERS; ++q) {
            float s = 0.0f;
#pragma unroll
            for (int c = 0; c < 4; ++c) {
                const int k = tid + 256 * c;
                const float p = (float)g_hist[q * K_CODES + k] * (1.0f / (float)M_TOT);
                g_hist[q * K_CODES + k] = 0;
                s += p * logf(p + 1e-7f);
            }
            red[tid] = s;
            __syncthreads();
            for (int off = 128; off > 0; off >>= 1) {
                if (tid < off) red[tid] += red[tid + off];
                __syncthreads();
            }
            if (tid == 0) sperp[q] = expf(-red[0]);
            __syncthreads();
        }
        if (tid == 0) {
            double cs = 0.0;
            float  ps = 0.0f;
            for (int q = 0; q < Q_LAYERS; ++q) {
                cs += g_commit[q] / (double)((double)M_TOT * (double)C_DIM);
                ps += sperp[q];
            }
            out[OUT_QOUT_ELEMS + OUT_IDX_ELEMS + 0] = (float)(cs / (double)Q_LAYERS);
            out[OUT_QOUT_ELEMS + OUT_IDX_ELEMS + 1] = ps / (float)Q_LAYERS;
        }
    }
}

// ---------------------------------------------------------------------------
extern "C" void kernel_launch(void* const* d_in, const int* in_sizes, int n_in,
                              void* d_out, int out_size)
{
    const float* x         = (const float*)d_in[0];
    const float* codebooks = (const float*)d_in[1];
    float* out = (float*)d_out;
    (void)in_sizes; (void)n_in; (void)out_size;

    static bool attr_set = false;
    if (!attr_set) {
        cudaFuncSetAttribute(rvq_fused_kernel,
                             cudaFuncAttributeMaxDynamicSharedMemorySize, SMEM_BYTES);
        attr_set = true;
    }

    prep_kernel<<<PREP_BLOCKS, 256>>>(x, codebooks);
    rvq_fused_kernel<<<M_TOT / M_TILE, 256, SMEM_BYTES>>>(codebooks);
    finish_kernel<<<FIN_BLOCKS, 256>>>(x, out);
}

// round 16
// speedup vs baseline: 1.0339x; 1.0339x over previous
#include <cuda_runtime.h>
#include <cuda_bf16.h>
#include <cstdint>

// ---------------- problem constants ----------------
#define B_DIM    64
#define C_DIM    512
#define T_DIM    256
#define Q_LAYERS 6
#define K_CODES  1024
#define M_TOT    (B_DIM * T_DIM)                    // 16384
#define OUT_QOUT_ELEMS (B_DIM * C_DIM * T_DIM)      // 8388608
#define OUT_IDX_ELEMS  (B_DIM * T_DIM * Q_LAYERS)   // 98304

// ---------------- GEMM tiling (bf16, 2-stage, KC=64) ----------------
#define M_TILE   64
#define N_TILE   256
#define N_PASSES (K_CODES / N_TILE)  // 4
#define KC       64                  // bf16 k-elems per staged chunk (128B/row)
#define K_CHUNKS (C_DIM / KC)        // 8 per pass
#define TOT_CHUNKS (N_PASSES * K_CHUNKS)  // 32 per layer
#define ROWB     144                 // 128B data + 16B pad (conflict-free ldmatrix)
#define A_BYTES  (M_TILE * ROWB)     // 9216
#define B_BYTES  (N_TILE * ROWB)     // 36864
#define STAGE_BYTES (A_BYTES + B_BYTES)      // 46080
#define MERGE_OFF   (2 * STAGE_BYTES)        // 92160
#define SMEM_BYTES  (MERGE_OFF + 9280)       // 101440 (2 CTAs/SM)

// ---------------- device scratch ----------------
__device__ __align__(16) float          g_X [M_TOT * C_DIM];
__device__ __align__(16) __nv_bfloat16  g_Xb[M_TOT * C_DIM];
__device__ __align__(16) __nv_bfloat16  g_CBb[Q_LAYERS * K_CODES * C_DIM];
__device__ int    g_idx[Q_LAYERS * M_TOT];
__device__ float  g_norm[Q_LAYERS * K_CODES];
__device__ int    g_hist[Q_LAYERS * K_CODES];
__device__ double g_commit[Q_LAYERS];

// ---------------- helpers ----------------
__device__ __forceinline__ uint32_t smem_u32(const void* p) {
    uint32_t a;
    asm("{ .reg .u64 t; cvta.to.shared.u64 t, %1; cvt.u32.u64 %0, t; }" : "=r"(a) : "l"(p));
    return a;
}
__device__ __forceinline__ void cp_async16(uint32_t dst, const void* src) {
    asm volatile("cp.async.cg.shared.global [%0], [%1], 16;" :: "r"(dst), "l"(src));
}
__device__ __forceinline__ void cp_commit() {
    asm volatile("cp.async.commit_group;" ::: "memory");
}
template <int N> __device__ __forceinline__ void cp_wait() {
    asm volatile("cp.async.wait_group %0;" :: "n"(N) : "memory");
}
__device__ __forceinline__ void ldsm_x4(uint32_t& r0, uint32_t& r1,
                                        uint32_t& r2, uint32_t& r3, uint32_t addr) {
    asm volatile("ldmatrix.sync.aligned.m8n8.x4.shared.b16 {%0,%1,%2,%3}, [%4];"
                 : "=r"(r0), "=r"(r1), "=r"(r2), "=r"(r3) : "r"(addr));
}
__device__ __forceinline__ void mma_bf16(float* c, const uint32_t* a,
                                         uint32_t b0, uint32_t b1) {
    asm volatile(
        "mma.sync.aligned.m16n8k16.row.col.f32.bf16.bf16.f32 "
        "{%0,%1,%2,%3}, {%4,%5,%6,%7}, {%8,%9}, {%0,%1,%2,%3};"
        : "+f"(c[0]), "+f"(c[1]), "+f"(c[2]), "+f"(c[3])
        : "r"(a[0]), "r"(a[1]), "r"(a[2]), "r"(a[3]), "r"(b0), "r"(b1));
}

__device__ __forceinline__ void ins4(float s, int n, float v[4], int ix[4]) {
    if (s < v[3]) {
        if (s < v[1]) {
            if (s < v[0]) { v[3]=v[2];ix[3]=ix[2]; v[2]=v[1];ix[2]=ix[1];
                            v[1]=v[0];ix[1]=ix[0]; v[0]=s;ix[0]=n; }
            else          { v[3]=v[2];ix[3]=ix[2]; v[2]=v[1];ix[2]=ix[1];
                            v[1]=s;ix[1]=n; }
        } else {
            if (s < v[2]) { v[3]=v[2];ix[3]=ix[2]; v[2]=s;ix[2]=n; }
            else          { v[3]=s;ix[3]=n; }
        }
    }
}
__device__ __forceinline__ bool lexlt(float s, int n, float v, int i) {
    return (s < v) || (s == v && n < i);
}
__device__ __forceinline__ void ins4lex(float s, int n, float v[4], int ix[4]) {
    if (lexlt(s, n, v[3], ix[3])) {
        if (lexlt(s, n, v[1], ix[1])) {
            if (lexlt(s, n, v[0], ix[0])) { v[3]=v[2];ix[3]=ix[2]; v[2]=v[1];ix[2]=ix[1];
                                            v[1]=v[0];ix[1]=ix[0]; v[0]=s;ix[0]=n; }
            else                          { v[3]=v[2];ix[3]=ix[2]; v[2]=v[1];ix[2]=ix[1];
                                            v[1]=s;ix[1]=n; }
        } else {
            if (lexlt(s, n, v[2], ix[2])) { v[3]=v[2];ix[3]=ix[2]; v[2]=s;ix[2]=n; }
            else                          { v[3]=s;ix[3]=n; }
        }
    }
}

// ---------------------------------------------------------------------------
// 1) prep: transpose x -> g_X/g_Xb  AND  norms + bf16 codebook
// ---------------------------------------------------------------------------
#define PREP_TR_BLOCKS 8192
#define PREP_BLOCKS    (PREP_TR_BLOCKS + Q_LAYERS * K_CODES)

__global__ __launch_bounds__(256) void prep_kernel(
    const float* __restrict__ x, const float* __restrict__ codebooks)
{
    __shared__ float sred[32 * 33];
    const int bid = blockIdx.x;
    const int tid = threadIdx.x;

    if (bid < PREP_TR_BLOCKS) {
        const int b  = bid >> 7;
        const int r  = bid & 127;
        const int c0 = (r >> 3) * 32;
        const int t0 = (r & 7) * 32;
        const int tx = tid & 31;
        const int ty = tid >> 5;
        float (*tile)[33] = reinterpret_cast<float(*)[33]>(sred);

        const float* xp = x + (size_t)b * C_DIM * T_DIM;
#pragma unroll
        for (int i = ty; i < 32; i += 8)
            tile[i][tx] = xp[(size_t)(c0 + i) * T_DIM + t0 + tx];
        __syncthreads();
#pragma unroll
        for (int i = ty; i < 32; i += 8) {
            const float vv = tile[tx][i];
            const size_t o = (size_t)(b * T_DIM + t0 + i) * C_DIM + c0 + tx;
            g_X[o]  = vv;
            g_Xb[o] = __float2bfloat16(vv);
        }
    } else {
        const int gk = bid - PREP_TR_BLOCKS;            // 0 .. 6143
        const float2 c = reinterpret_cast<const float2*>(codebooks + (size_t)gk * C_DIM)[tid];
        sred[tid] = c.x * c.x + c.y * c.y;
        __nv_bfloat162 h = {__float2bfloat16(c.x), __float2bfloat16(c.y)};
        reinterpret_cast<__nv_bfloat162*>(g_CBb + (size_t)gk * C_DIM)[tid] = h;
        __syncthreads();
        for (int off = 128; off > 0; off >>= 1) {
            if (tid < off) sred[tid] += sred[tid + off];
            __syncthreads();
        }
        if (tid == 0) {
            g_norm[gk] = sred[0];
            if (gk < Q_LAYERS) g_commit[gk] = 0.0;
        }
    }
}

// ---------------------------------------------------------------------------
// 2) Persistent fused kernel: all 6 layers (bf16 mma) + cross-layer prestage
// ---------------------------------------------------------------------------
__device__ __forceinline__ void stage_A_chunk(uint32_t sbase, int buf, int cidx,
                                              int m0, int tid)
{
    const int kw = (cidx & 7) * KC;
    const uint32_t ab = sbase + (uint32_t)(buf * STAGE_BYTES);
#pragma unroll
    for (int i = 0; i < 2; ++i) {
        const int idx = tid + 256 * i;
        const int row = idx >> 3, g = idx & 7;
        cp_async16(ab + (uint32_t)(row * ROWB + g * 16),
                   g_Xb + (size_t)(m0 + row) * C_DIM + kw + g * 8);
    }
}
__device__ __forceinline__ void stage_B_chunk(uint32_t sbase, int buf, int cidx,
                                              const __nv_bfloat16* __restrict__ cbb,
                                              int tid)
{
    const int nt = cidx >> 3;
    const int kw = (cidx & 7) * KC;
    const uint32_t bb = sbase + (uint32_t)(buf * STAGE_BYTES) + A_BYTES;
    const __nv_bfloat16* bsrc = cbb + (size_t)(nt * N_TILE) * C_DIM + kw;
#pragma unroll
    for (int i = 0; i < 8; ++i) {
        const int idx = tid + 256 * i;
        const int row = idx >> 3, g = idx & 7;
        cp_async16(bb + (uint32_t)(row * ROWB + g * 16),
                   bsrc + (size_t)row * C_DIM + g * 8);
    }
}

__global__ __launch_bounds__(256, 2) void rvq_fused_kernel(
    const float* __restrict__ cbf0)
{
    extern __shared__ char sm[];
    const uint32_t sbase = smem_u32(sm);

    const int tid  = threadIdx.x;
    const int wid  = tid >> 5;
    const int lane = tid & 31;
    const int wr   = wid & 1;
    const int wc   = wid >> 1;
    const int lg   = lane >> 2;
    const int lt   = lane & 3;
    const int m0   = blockIdx.x * M_TILE;

    const uint32_t aoff0 = (uint32_t)((wr * 32 + (lane & 15)) * ROWB + (lane >> 4) * 16);
    const uint32_t aoff1 = aoff0 + 16 * ROWB;
    const uint32_t boff  = (uint32_t)((wc * 64 + (lane & 7) + ((lane >> 4) << 3)) * ROWB
                                      + (((lane >> 3) & 1) * 16));

    float* smV = (float*)(sm + MERGE_OFF);          // [4][64][4]
    int*   smI = (int*)(sm + MERGE_OFF + 4096);     // [4][64][4]
    int*   sFi = (int*)(sm + MERGE_OFF + 8192);     // [64][4]
    float* sCm = (float*)(sm + MERGE_OFF + 9216);   // [8]

    for (int q = 0; q < Q_LAYERS; ++q) {
        const __nv_bfloat16* __restrict__ cbb = g_CBb + (size_t)q * K_CODES * C_DIM;
        const float* __restrict__ cbf  = cbf0 + (size_t)q * K_CODES * C_DIM;
        const float* __restrict__ norms = g_norm + q * K_CODES;

        float v[4][4];
        int   ix[4][4];
#pragma unroll
        for (int r = 0; r < 4; ++r)
#pragma unroll
            for (int j = 0; j < 4; ++j) { v[r][j] = 3.4e38f; ix[r][j] = 0; }

        if (q == 0) {
            __syncthreads();
            stage_A_chunk(sbase, 0, 0, m0, tid);
            stage_B_chunk(sbase, 0, 0, cbb, tid);
            cp_commit();
        }
        // q > 0: chunk 0 prestaged across the layer boundary

        for (int nt = 0; nt < N_PASSES; ++nt) {
            float acc[2][8][4];
#pragma unroll
            for (int s = 0; s < 2; ++s)
#pragma unroll
                for (int ns = 0; ns < 8; ++ns)
#pragma unroll
                    for (int j = 0; j < 4; ++j) acc[s][ns][j] = 0.0f;

#pragma unroll 1
            for (int kc = 0; kc < K_CHUNKS; ++kc) {
                const int cidx = nt * K_CHUNKS + kc;
                cp_wait<0>();
                __syncthreads();
                if (cidx + 1 < TOT_CHUNKS) {
                    stage_A_chunk(sbase, (cidx + 1) & 1, cidx + 1, m0, tid);
                    stage_B_chunk(sbase, (cidx + 1) & 1, cidx + 1, cbb, tid);
                    cp_commit();
                }

                const uint32_t Ab = sbase + (uint32_t)((cidx & 1) * STAGE_BYTES);
                const uint32_t Bb = Ab + A_BYTES;

#pragma unroll
                for (int ks = 0; ks < 4; ++ks) {
                    const uint32_t kb = (uint32_t)(ks * 32);
                    uint32_t a[2][4];
                    ldsm_x4(a[0][0], a[0][1], a[0][2], a[0][3], Ab + aoff0 + kb);
                    ldsm_x4(a[1][0], a[1][1], a[1][2], a[1][3], Ab + aoff1 + kb);
#pragma unroll
                    for (int p = 0; p < 4; ++p) {
                        uint32_t b0, b1, b2, b3;
                        ldsm_x4(b0, b1, b2, b3, Bb + boff + (uint32_t)(p * 16 * ROWB) + kb);
                        mma_bf16(acc[0][2 * p    ], a[0], b0, b1);
                        mma_bf16(acc[1][2 * p    ], a[1], b0, b1);
                        mma_bf16(acc[0][2 * p + 1], a[0], b2, b3);
                        mma_bf16(acc[1][2 * p + 1], a[1], b2, b3);
                    }
                }
            }

            const int nbase = nt * N_TILE + wc * 64 + lt * 2;
#pragma unroll
            for (int s = 0; s < 2; ++s) {
#pragma unroll
                for (int ns = 0; ns < 8; ++ns) {
                    const int n = nbase + ns * 8;
                    const float nm0 = __ldg(&norms[n]);
                    const float nm1 = __ldg(&norms[n + 1]);
                    ins4(fmaf(-2.0f, acc[s][ns][0], nm0), n,     v[s*2+0], ix[s*2+0]);
                    ins4(fmaf(-2.0f, acc[s][ns][1], nm1), n + 1, v[s*2+0], ix[s*2+0]);
                    ins4(fmaf(-2.0f, acc[s][ns][2], nm0), n,     v[s*2+1], ix[s*2+1]);
                    ins4(fmaf(-2.0f, acc[s][ns][3], nm1), n + 1, v[s*2+1], ix[s*2+1]);
                }
            }
        }

#pragma unroll
        for (int r = 0; r < 4; ++r) {
#pragma unroll
            for (int o = 1; o <= 2; o <<= 1) {
                float ov[4]; int oi[4];
#pragma unroll
                for (int j = 0; j < 4; ++j) {
                    ov[j] = __shfl_xor_sync(0xffffffffu, v[r][j], o);
                    oi[j] = __shfl_xor_sync(0xffffffffu, ix[r][j], o);
                }
#pragma unroll
                for (int j = 0; j < 4; ++j) ins4lex(ov[j], oi[j], v[r], ix[r]);
            }
        }

        __syncthreads();
        if (lt == 0) {
#pragma unroll
            for (int r = 0; r < 4; ++r) {
                const int row = wr * 32 + (r >> 1) * 16 + (r & 1) * 8 + lg;
#pragma unroll
                for (int j = 0; j < 4; ++j) {
                    smV[(wc * 64 + row) * 4 + j] = v[r][j];
                    smI[(wc * 64 + row) * 4 + j] = ix[r][j];
                }
            }
        }
        __syncthreads();
        if (wid < 2) {
            const int row = wid * 32 + lane;
            float fv[4]; int fi[4];
#pragma unroll
            for (int j = 0; j < 4; ++j) { fv[j] = 3.4e38f; fi[j] = 0x7fffffff; }
#pragma unroll
            for (int h = 0; h < 4; ++h)
#pragma unroll
                for (int j = 0; j < 4; ++j)
                    ins4lex(smV[(h * 64 + row) * 4 + j], smI[(h * 64 + row) * 4 + j], fv, fi);
#pragma unroll
            for (int j = 0; j < 4; ++j) sFi[row * 4 + j] = fi[j];
        }
        __syncthreads();

        if (q + 1 < Q_LAYERS) {
            stage_B_chunk(sbase, 0, 0, g_CBb + (size_t)(q + 1) * K_CODES * C_DIM, tid);
            cp_commit();
        }

        // ---------------- exact fp32 fixup + residual update ----------------
        float warp_commit = 0.0f;
        int* hist_q = g_hist + q * K_CODES;

#pragma unroll 1
        for (int i = 0; i < 8; ++i) {
            const int row = wid * 8 + i;
            const int m   = m0 + row;
            int cand[4];
#pragma unroll
            for (int c = 0; c < 4; ++c) cand[c] = sFi[row * 4 + c];

            const float4* xp = reinterpret_cast<const float4*>(g_X + (size_t)m * C_DIM);
            float4 xv[4];
#pragma unroll
            for (int j = 0; j < 4; ++j) xv[j] = xp[lane + 32 * j];

            float d[4];
#pragma unroll
            for (int c = 0; c < 4; ++c) {
                const float4* cp = reinterpret_cast<const float4*>(cbf + (size_t)cand[c] * C_DIM);
                float s = 0.0f;
#pragma unroll
                for (int j = 0; j < 4; ++j) {
                    const float4 cv = cp[lane + 32 * j];
                    const float dx = xv[j].x - cv.x, dy = xv[j].y - cv.y;
                    const float dz = xv[j].z - cv.z, dw = xv[j].w - cv.w;
                    s += dx * dx + dy * dy + dz * dz + dw * dw;
                }
                d[c] = s;
            }
#pragma unroll
            for (int c = 0; c < 4; ++c)
#pragma unroll
                for (int o = 16; o > 0; o >>= 1)
                    d[c] += __shfl_xor_sync(0xffffffffu, d[c], o);

            float best = d[0]; int bi = cand[0];
#pragma unroll
            for (int c = 1; c < 4; ++c) {
                if (d[c] < best || (d[c] == best && cand[c] < bi)) {
                    best = d[c]; bi = cand[c];
                }
            }

            const float4* bp = reinterpret_cast<const float4*>(cbf + (size_t)bi * C_DIM);
            float4* xo = reinterpret_cast<float4*>(g_X + (size_t)m * C_DIM);
            uint2*  xb = reinterpret_cast<uint2*>(g_Xb + (size_t)m * C_DIM);
#pragma unroll
            for (int j = 0; j < 4; ++j) {
                const float4 cv = bp[lane + 32 * j];
                float4 r;
                r.x = xv[j].x - cv.x; r.y = xv[j].y - cv.y;
                r.z = xv[j].z - cv.z; r.w = xv[j].w - cv.w;
                xo[lane + 32 * j] = r;
                __nv_bfloat162 h0 = {__float2bfloat16(r.x), __float2bfloat16(r.y)};
                __nv_bfloat162 h1 = {__float2bfloat16(r.z), __float2bfloat16(r.w)};
                uint2 pk;
                pk.x = *reinterpret_cast<uint32_t*>(&h0);
                pk.y = *reinterpret_cast<uint32_t*>(&h1);
                xb[lane + 32 * j] = pk;
            }

            if (lane == 0) {
                warp_commit += best;
                g_idx[q * M_TOT + m] = bi;
                atomicAdd(&hist_q[bi], 1);
            }
        }

        if (lane == 0) sCm[wid] = warp_commit;
        __syncthreads();     // orders g_Xb writes before next-layer A staging (block scope)
        if (tid == 0) {
            float cs = 0.0f;
#pragma unroll
            for (int w = 0; w < 8; ++w) cs += sCm[w];
            atomicAdd(&g_commit[q], (double)cs);
        }

        if (q + 1 < Q_LAYERS) {
            stage_A_chunk(sbase, 0, 0, m0, tid);
            cp_commit();
        }
    }
}

// ---------------------------------------------------------------------------
// 3) finish: qout = x - final_residual (transposed), idx out, perp + scalars
// ---------------------------------------------------------------------------
#define FIN_QOUT_BLOCKS 8192
#define FIN_IDX_BLOCKS  (OUT_IDX_ELEMS / 256)       // 384
#define FIN_BLOCKS      (FIN_QOUT_BLOCKS + FIN_IDX_BLOCKS + 1)

__global__ __launch_bounds__(256) void finish_kernel(
    const float* __restrict__ x, float* __restrict__ out)
{
    const int bid = blockIdx.x;
    const int tid = threadIdx.x;

    if (bid < FIN_QOUT_BLOCKS) {
        __shared__ float tile[32][33];
        const int b  = bid >> 7;
        const int r  = bid & 127;
        const int c0 = (r >> 3) * 32;
        const int t0 = (r & 7) * 32;
        const int tx = tid & 31;
        const int ty = tid >> 5;

#pragma unroll
        for (int i = ty; i < 32; i += 8)
            tile[i][tx] = g_X[(size_t)(b * T_DIM + t0 + i) * C_DIM + c0 + tx];
        __syncthreads();

        const float* xp = x + (size_t)b * C_DIM * T_DIM;
        float* op = out + (size_t)b * C_DIM * T_DIM;
#pragma unroll
        for (int i = ty; i < 32; i += 8) {
            const size_t o = (size_t)(c0 + i) * T_DIM + t0 + tx;
            op[o] = xp[o] - tile[tx][i];
        }
    } else if (bid < FIN_QOUT_BLOCKS + FIN_IDX_BLOCKS) {
        const int i = (bid - FIN_QOUT_BLOCKS) * 256 + tid;
        const int m = i / Q_LAYERS;
        const int q = i - m * Q_LAYERS;
        out[OUT_QOUT_ELEMS + i] = (float)g_idx[q * M_TOT + m];
    } else {
        __shared__ float red[256];
        __shared__ float sperp[Q_LAYERS];
        for (int q = 0; q < Q_LAYERS; ++q) {
            float s = 0.0f;
#pragma unroll
            for (int c = 0; c < 4; ++c) {
                const int k = tid + 256 * c;
                const float p = (float)g_hist[q * K_CODES + k] * (1.0f / (float)M_TOT);
                g_hist[q * K_CODES + k] = 0;
                s += p * logf(p + 1e-7f);
            }
            red[tid] = s;
            __syncthreads();
            for (int off = 128; off > 0; off >>= 1) {
                if (tid < off) red[tid] += red[tid + off];
                __syncthreads();
            }
            if (tid == 0) sperp[q] = expf(-red[0]);
            __syncthreads();
        }
        if (tid == 0) {
            double cs = 0.0;
            float  ps = 0.0f;
            for (int q = 0; q < Q_LAYERS; ++q) {
                cs += g_commit[q] / (double)((double)M_TOT * (double)C_DIM);
                ps += sperp[q];
            }
            out[OUT_QOUT_ELEMS + OUT_IDX_ELEMS + 0] = (float)(cs / (double)Q_LAYERS);
            out[OUT_QOUT_ELEMS + OUT_IDX_ELEMS + 1] = ps / (float)Q_LAYERS;
        }
    }
}

// ---------------------------------------------------------------------------
extern "C" void kernel_launch(void* const* d_in, const int* in_sizes, int n_in,
                              void* d_out, int out_size)
{
    const float* x         = (const float*)d_in[0];
    const float* codebooks = (const float*)d_in[1];
    float* out = (float*)d_out;
    (void)in_sizes; (void)n_in; (void)out_size;

    static bool attr_set = false;
    if (!attr_set) {
        cudaFuncSetAttribute(rvq_fused_kernel,
                             cudaFuncAttributeMaxDynamicSharedMemorySize, SMEM_BYTES);
        attr_set = true;
    }

    prep_kernel<<<PREP_BLOCKS, 256>>>(x, codebooks);
    rvq_fused_kernel<<<M_TOT / M_TILE, 256, SMEM_BYTES>>>(codebooks);
    finish_kernel<<<FIN_BLOCKS, 256>>>(x, out);
}